// round 1
// baseline (speedup 1.0000x reference)
#include <cuda_runtime.h>
#include <cuda_bf16.h>

// Problem constants
#define BATCH 2
#define SEQ   2048
#define DIM   1024
#define HEADS 16
#define HDIM  64
#define MROWS (BATCH*SEQ)   // 4096

// Scratch (allocation-free rule: __device__ globals)
__device__ float g_q [MROWS * DIM];
__device__ float g_k [MROWS * DIM];
__device__ float g_v [MROWS * DIM];
__device__ float g_ao[MROWS * DIM];

// ---------------------------------------------------------------------------
// Tiled fp32 GEMM: C[M,N] = A[M,K] @ B[K,N], all row-major.
// 64x64 output tile, K-step 16, 256 threads, 4x4 register micro-tile.
// M % 64 == 0, N % 64 == 0, K % 16 == 0 (holds: 4096/1024/1024).
// ---------------------------------------------------------------------------
__global__ __launch_bounds__(256) void gemm_kernel(
    const float* __restrict__ A, const float* __restrict__ B,
    float* __restrict__ C, int M, int N, int K)
{
    __shared__ float As[16][64 + 1];   // As[k][m]
    __shared__ float Bs[16][64 + 1];   // Bs[k][n]

    const int tid = threadIdx.x;
    const int tx = tid & 15;           // 0..15 -> 4 cols each
    const int ty = tid >> 4;           // 0..15 -> 4 rows each
    const int bm = blockIdx.y * 64;
    const int bn = blockIdx.x * 64;

    float acc[4][4] = {};

    for (int k0 = 0; k0 < K; k0 += 16) {
        // Load A tile (64 rows x 16 k), transposed into As[k][m]
        #pragma unroll
        for (int i = tid; i < 64 * 16; i += 256) {
            int m  = i >> 4;
            int kk = i & 15;
            As[kk][m] = A[(size_t)(bm + m) * K + k0 + kk];
        }
        // Load B tile (16 k x 64 n), coalesced along n
        #pragma unroll
        for (int i = tid; i < 16 * 64; i += 256) {
            int kk = i >> 6;
            int n  = i & 63;
            Bs[kk][n] = B[(size_t)(k0 + kk) * N + bn + n];
        }
        __syncthreads();

        #pragma unroll
        for (int kk = 0; kk < 16; kk++) {
            float a[4], b[4];
            #pragma unroll
            for (int i = 0; i < 4; i++) a[i] = As[kk][ty * 4 + i];
            #pragma unroll
            for (int j = 0; j < 4; j++) b[j] = Bs[kk][tx * 4 + j];
            #pragma unroll
            for (int i = 0; i < 4; i++)
                #pragma unroll
                for (int j = 0; j < 4; j++)
                    acc[i][j] += a[i] * b[j];
        }
        __syncthreads();
    }

    #pragma unroll
    for (int i = 0; i < 4; i++)
        #pragma unroll
        for (int j = 0; j < 4; j++)
            C[(size_t)(bm + ty * 4 + i) * N + bn + tx * 4 + j] = acc[i][j];
}

// ---------------------------------------------------------------------------
// Fused flash-attention (fp32, online softmax).
// Block = one (batch, head, 64-row Q tile). Streams 32-row K/V tiles.
// q is UNscaled here; scale 1/sqrt(64) applied to the scores.
// Mask: additive (1-m)*(-3e38) semantics (matches ref softmax incl. all-masked
// rows, which become uniform).
// ---------------------------------------------------------------------------
__global__ __launch_bounds__(256) void attn_kernel(
    const float* __restrict__ q, const float* __restrict__ k,
    const float* __restrict__ v, const int* __restrict__ mask,
    float* __restrict__ o)
{
    __shared__ float Qs[64][65];
    __shared__ float Ks[32][65];
    __shared__ float Vs[32][65];
    __shared__ float Ps[64][33];
    __shared__ float corr[64], rowm[64], rowl[64];
    __shared__ int   msk[32];

    const int b  = blockIdx.z;
    const int h  = blockIdx.y;
    const int qt = blockIdx.x;
    const int tid = threadIdx.x;
    const int tx = tid & 15;   // 0..15
    const int ty = tid >> 4;   // 0..15
    const float scale = 0.125f;  // HDIM^-0.5

    const size_t base_q = ((size_t)(b * SEQ) + qt * 64) * DIM + h * HDIM;

    // Load Q tile (64 rows x 64 dims)
    #pragma unroll
    for (int i = tid; i < 64 * 64; i += 256) {
        int r = i >> 6, c = i & 63;
        Qs[r][c] = q[base_q + (size_t)r * DIM + c];
    }
    if (tid < 64) { rowm[tid] = -3.0e38f; rowl[tid] = 0.0f; }

    float acc[4][4] = {};
    __syncthreads();

    for (int kt = 0; kt < SEQ / 32; kt++) {
        const size_t base_k = ((size_t)(b * SEQ) + kt * 32) * DIM + h * HDIM;
        #pragma unroll
        for (int i = tid; i < 32 * 64; i += 256) {
            int r = i >> 6, c = i & 63;
            Ks[r][c] = k[base_k + (size_t)r * DIM + c];
            Vs[r][c] = v[base_k + (size_t)r * DIM + c];
        }
        if (tid < 32) msk[tid] = mask[b * SEQ + kt * 32 + tid];
        __syncthreads();

        // Scores: rows ty*4..+3, cols tx*2..+1 over this 32-key tile
        float sv[4][2] = {};
        #pragma unroll
        for (int d = 0; d < 64; d++) {
            float a0 = Qs[ty * 4 + 0][d];
            float a1 = Qs[ty * 4 + 1][d];
            float a2 = Qs[ty * 4 + 2][d];
            float a3 = Qs[ty * 4 + 3][d];
            float b0 = Ks[tx * 2 + 0][d];
            float b1 = Ks[tx * 2 + 1][d];
            sv[0][0] += a0 * b0; sv[0][1] += a0 * b1;
            sv[1][0] += a1 * b0; sv[1][1] += a1 * b1;
            sv[2][0] += a2 * b0; sv[2][1] += a2 * b1;
            sv[3][0] += a3 * b0; sv[3][1] += a3 * b1;
        }
        #pragma unroll
        for (int i = 0; i < 4; i++)
            #pragma unroll
            for (int j = 0; j < 2; j++) {
                float x = sv[i][j] * scale;
                if (msk[tx * 2 + j] == 0) x = -3.0e38f;
                Ps[ty * 4 + i][tx * 2 + j] = x;
            }
        __syncthreads();

        // Online softmax per row (one thread per row)
        if (tid < 64) {
            int r = tid;
            float m0 = rowm[r];
            float tm = m0;
            #pragma unroll
            for (int j = 0; j < 32; j++) tm = fmaxf(tm, Ps[r][j]);
            float c = __expf(m0 - tm);
            float l = rowl[r] * c;
            #pragma unroll
            for (int j = 0; j < 32; j++) {
                float p = __expf(Ps[r][j] - tm);
                Ps[r][j] = p;
                l += p;
            }
            rowm[r] = tm; rowl[r] = l; corr[r] = c;
        }
        __syncthreads();

        // Rescale accumulator, add P @ V for this tile
        #pragma unroll
        for (int i = 0; i < 4; i++) {
            float c = corr[ty * 4 + i];
            #pragma unroll
            for (int j = 0; j < 4; j++) acc[i][j] *= c;
        }
        #pragma unroll
        for (int kk = 0; kk < 32; kk++) {
            float p0 = Ps[ty * 4 + 0][kk];
            float p1 = Ps[ty * 4 + 1][kk];
            float p2 = Ps[ty * 4 + 2][kk];
            float p3 = Ps[ty * 4 + 3][kk];
            float b0 = Vs[kk][tx * 4 + 0];
            float b1 = Vs[kk][tx * 4 + 1];
            float b2 = Vs[kk][tx * 4 + 2];
            float b3 = Vs[kk][tx * 4 + 3];
            acc[0][0] += p0 * b0; acc[0][1] += p0 * b1; acc[0][2] += p0 * b2; acc[0][3] += p0 * b3;
            acc[1][0] += p1 * b0; acc[1][1] += p1 * b1; acc[1][2] += p1 * b2; acc[1][3] += p1 * b3;
            acc[2][0] += p2 * b0; acc[2][1] += p2 * b1; acc[2][2] += p2 * b2; acc[2][3] += p2 * b3;
            acc[3][0] += p3 * b0; acc[3][1] += p3 * b1; acc[3][2] += p3 * b2; acc[3][3] += p3 * b3;
        }
        __syncthreads();
    }

    // Epilogue: normalize and write [b, s, h*64+c] layout (ready for Wo GEMM)
    #pragma unroll
    for (int i = 0; i < 4; i++) {
        float inv = 1.0f / rowl[ty * 4 + i];
        #pragma unroll
        for (int j = 0; j < 4; j++)
            o[base_q + (size_t)(ty * 4 + i) * DIM + tx * 4 + j] = acc[i][j] * inv;
    }
}

// ---------------------------------------------------------------------------
// kernel_launch: H->Q/K/V projections, fused attention, output projection.
// Graph-capturable: kernel launches only on the default stream.
// ---------------------------------------------------------------------------
extern "C" void kernel_launch(void* const* d_in, const int* in_sizes, int n_in,
                              void* d_out, int out_size)
{
    const float* H    = (const float*)d_in[0];
    const int*   mask = (const int*)  d_in[1];
    const float* Wq   = (const float*)d_in[2];
    const float* Wk   = (const float*)d_in[3];
    const float* Wv   = (const float*)d_in[4];
    const float* Wo   = (const float*)d_in[5];
    float* out = (float*)d_out;

    float *q, *k, *v, *ao;
    cudaGetSymbolAddress((void**)&q,  g_q);
    cudaGetSymbolAddress((void**)&k,  g_k);
    cudaGetSymbolAddress((void**)&v,  g_v);
    cudaGetSymbolAddress((void**)&ao, g_ao);

    dim3 gg(DIM / 64, MROWS / 64);   // (16, 64)
    gemm_kernel<<<gg, 256>>>(H, Wq, q, MROWS, DIM, DIM);
    gemm_kernel<<<gg, 256>>>(H, Wk, k, MROWS, DIM, DIM);
    gemm_kernel<<<gg, 256>>>(H, Wv, v, MROWS, DIM, DIM);

    dim3 ga(SEQ / 64, HEADS, BATCH); // (32, 16, 2)
    attn_kernel<<<ga, 256>>>(q, k, v, mask, ao);

    gemm_kernel<<<gg, 256>>>(ao, Wo, out, MROWS, DIM, DIM);
}

// round 3
// speedup vs baseline: 1.7589x; 1.7589x over previous
#include <cuda_runtime.h>
#include <cuda_bf16.h>
#include <cstdint>

// Problem constants
#define BATCH 2
#define SEQ   2048
#define DIM   1024
#define HEADS 16
#define HDIM  64
#define MROWS (BATCH*SEQ)   // 4096

// Scratch (allocation-free rule: __device__ globals)
__device__ float g_q [MROWS * DIM];
__device__ float g_k [MROWS * DIM];
__device__ float g_v [MROWS * DIM];
__device__ float g_ao[MROWS * DIM];
__device__ float g_wt[4 * DIM * DIM];   // transposed weights [N][K]

// ---------------------------------------------------------------------------
// helpers
// ---------------------------------------------------------------------------
__device__ __forceinline__ uint32_t smem_u32(const void* p) {
    uint32_t a;
    asm("{ .reg .u64 t; cvta.to.shared.u64 t, %1; cvt.u32.u64 %0, t; }"
        : "=r"(a) : "l"(p));
    return a;
}
__device__ __forceinline__ void cp16(uint32_t dst, const void* src) {
    asm volatile("cp.async.cg.shared.global [%0], [%1], 16;"
                 :: "r"(dst), "l"(src));
}
#define CP_COMMIT() asm volatile("cp.async.commit_group;" ::: "memory")
#define CP_WAIT1()  asm volatile("cp.async.wait_group 1;" ::: "memory")
#define CP_WAIT0()  asm volatile("cp.async.wait_group 0;" ::: "memory")

__device__ __forceinline__ uint32_t f2tf32(float f) {
    uint32_t r;
    asm("cvt.rna.tf32.f32 %0, %1;" : "=r"(r) : "f"(f));
    return r;
}
__device__ __forceinline__ void mma_tf32(float* c,
    uint32_t a0, uint32_t a1, uint32_t a2, uint32_t a3,
    uint32_t b0, uint32_t b1)
{
    asm volatile(
        "mma.sync.aligned.m16n8k8.row.col.f32.tf32.tf32.f32 "
        "{%0,%1,%2,%3}, {%4,%5,%6,%7}, {%8,%9}, {%0,%1,%2,%3};"
        : "+f"(c[0]), "+f"(c[1]), "+f"(c[2]), "+f"(c[3])
        : "r"(a0), "r"(a1), "r"(a2), "r"(a3), "r"(b0), "r"(b1));
}

// ---------------------------------------------------------------------------
// Weight transpose: WT[n][k] = W[k][n], 1024x1024
// ---------------------------------------------------------------------------
__global__ __launch_bounds__(256) void transpose_kernel(
    const float* __restrict__ W, float* __restrict__ WT)
{
    __shared__ float t[32][33];
    int bx = blockIdx.x * 32, by = blockIdx.y * 32;
    int x = bx + threadIdx.x;
    #pragma unroll
    for (int j = 0; j < 32; j += 8)
        t[threadIdx.y + j][threadIdx.x] = W[(size_t)(by + threadIdx.y + j) * DIM + x];
    __syncthreads();
    x = by + threadIdx.x;
    #pragma unroll
    for (int j = 0; j < 32; j += 8)
        WT[(size_t)(bx + threadIdx.y + j) * DIM + x] = t[threadIdx.x][threadIdx.y + j];
}

// ---------------------------------------------------------------------------
// mma.sync tf32 GEMM: C[M,1024] = A[M,1024] @ BT[1024,1024]^T
//   BT is [N][K] row-major (i.e. W transposed).
// CTA tile 128x128, K-chunk 32, 8 warps in 2(M)x4(N), warp tile 64x32.
// Double-buffered cp.async smem, padded rows (stride 36 floats).
// ---------------------------------------------------------------------------
#define BM 128
#define BN 128
#define BK 32
#define LDP 36                       // padded row stride (floats)
#define TILE_FLOATS (128 * LDP)      // 4608 per operand tile
#define STAGE_FLOATS (2 * TILE_FLOATS)
#define GEMM_SMEM (2 * STAGE_FLOATS * 4)   // 73728 bytes
#define NCHUNK (DIM / BK)            // 32

__global__ __launch_bounds__(256, 2) void gemm_mma_kernel(
    const float* __restrict__ A, const float* __restrict__ BT,
    float* __restrict__ C)
{
    extern __shared__ float sm[];
    const uint32_t sbase = smem_u32(sm);
    const int tid = threadIdx.x;
    const int wid = tid >> 5;
    const int lid = tid & 31;
    const int wm  = wid >> 2;        // 0..1
    const int wn  = wid & 3;         // 0..3
    const int g   = lid >> 2;        // 0..7
    const int tg  = lid & 3;         // 0..3
    const int bm = blockIdx.y * BM;
    const int bn = blockIdx.x * BN;

    float acc[4][4][4] = {};         // [fm][fn][c0..c3]

    // ---- async tile loader: chunk c -> stage stg ----
    auto load_chunk = [&](int c, int stg) {
        const float* Ag = A  + (size_t)bm * DIM + c * BK;
        const float* Bg = BT + (size_t)bn * DIM + c * BK;
        const uint32_t aB = sbase + (uint32_t)(stg * STAGE_FLOATS) * 4;
        const uint32_t bB = aB + TILE_FLOATS * 4;
        #pragma unroll
        for (int i = 0; i < 4; i++) {
            int idx = tid + i * 256;       // 0..1023
            int r = idx >> 3, s = idx & 7; // row, 16B seg
            uint32_t off = (uint32_t)(r * LDP + s * 4) * 4;
            cp16(aB + off, Ag + (size_t)r * DIM + s * 4);
            cp16(bB + off, Bg + (size_t)r * DIM + s * 4);
        }
    };

    // ---- compute one 32-deep chunk from stage stg ----
    auto compute = [&](int stg) {
        const float* As = sm + stg * STAGE_FLOATS;
        const float* Bs = As + TILE_FLOATS;
        #pragma unroll
        for (int kk = 0; kk < 4; kk++) {
            const int k0 = kk * 8;
            uint32_t af[4][4], bf[4][2];
            #pragma unroll
            for (int fm = 0; fm < 4; fm++) {
                const float* ar = As + (wm * 64 + fm * 16 + g) * LDP + k0;
                af[fm][0] = f2tf32(ar[tg]);
                af[fm][1] = f2tf32(ar[8 * LDP + tg]);
                af[fm][2] = f2tf32(ar[tg + 4]);
                af[fm][3] = f2tf32(ar[8 * LDP + tg + 4]);
            }
            #pragma unroll
            for (int fn = 0; fn < 4; fn++) {
                const float* br = Bs + (wn * 32 + fn * 8 + g) * LDP + k0;
                bf[fn][0] = f2tf32(br[tg]);
                bf[fn][1] = f2tf32(br[tg + 4]);
            }
            #pragma unroll
            for (int fm = 0; fm < 4; fm++)
                #pragma unroll
                for (int fn = 0; fn < 4; fn++)
                    mma_tf32(acc[fm][fn], af[fm][0], af[fm][1], af[fm][2], af[fm][3],
                             bf[fn][0], bf[fn][1]);
        }
    };

    load_chunk(0, 0); CP_COMMIT();
    for (int c = 0; c < NCHUNK; c++) {
        if (c + 1 < NCHUNK) { load_chunk(c + 1, (c + 1) & 1); CP_COMMIT(); }
        if (c + 1 < NCHUNK) { CP_WAIT1(); } else { CP_WAIT0(); }
        __syncthreads();
        compute(c & 1);
        __syncthreads();
    }

    // Epilogue: c0/c1 at (row, col..col+1), c2/c3 at (row+8, ...)
    #pragma unroll
    for (int fm = 0; fm < 4; fm++) {
        const int row = bm + wm * 64 + fm * 16 + g;
        #pragma unroll
        for (int fn = 0; fn < 4; fn++) {
            const int col = bn + wn * 32 + fn * 8 + tg * 2;
            float2 lo = make_float2(acc[fm][fn][0], acc[fm][fn][1]);
            float2 hi = make_float2(acc[fm][fn][2], acc[fm][fn][3]);
            *(float2*)(C + (size_t)row * DIM + col)       = lo;
            *(float2*)(C + (size_t)(row + 8) * DIM + col) = hi;
        }
    }
}

// ---------------------------------------------------------------------------
// Fused flash-attention (fp32, online softmax) — unchanged (passing, R1).
// ---------------------------------------------------------------------------
__global__ __launch_bounds__(256) void attn_kernel(
    const float* __restrict__ q, const float* __restrict__ k,
    const float* __restrict__ v, const int* __restrict__ mask,
    float* __restrict__ o)
{
    __shared__ float Qs[64][65];
    __shared__ float Ks[32][65];
    __shared__ float Vs[32][65];
    __shared__ float Ps[64][33];
    __shared__ float corr[64], rowm[64], rowl[64];
    __shared__ int   msk[32];

    const int b  = blockIdx.z;
    const int h  = blockIdx.y;
    const int qt = blockIdx.x;
    const int tid = threadIdx.x;
    const int tx = tid & 15;
    const int ty = tid >> 4;
    const float scale = 0.125f;

    const size_t base_q = ((size_t)(b * SEQ) + qt * 64) * DIM + h * HDIM;

    #pragma unroll
    for (int i = tid; i < 64 * 64; i += 256) {
        int r = i >> 6, c = i & 63;
        Qs[r][c] = q[base_q + (size_t)r * DIM + c];
    }
    if (tid < 64) { rowm[tid] = -3.0e38f; rowl[tid] = 0.0f; }

    float acc[4][4] = {};
    __syncthreads();

    for (int kt = 0; kt < SEQ / 32; kt++) {
        const size_t base_k = ((size_t)(b * SEQ) + kt * 32) * DIM + h * HDIM;
        #pragma unroll
        for (int i = tid; i < 32 * 64; i += 256) {
            int r = i >> 6, c = i & 63;
            Ks[r][c] = k[base_k + (size_t)r * DIM + c];
            Vs[r][c] = v[base_k + (size_t)r * DIM + c];
        }
        if (tid < 32) msk[tid] = mask[b * SEQ + kt * 32 + tid];
        __syncthreads();

        float sv[4][2] = {};
        #pragma unroll
        for (int d = 0; d < 64; d++) {
            float a0 = Qs[ty * 4 + 0][d];
            float a1 = Qs[ty * 4 + 1][d];
            float a2 = Qs[ty * 4 + 2][d];
            float a3 = Qs[ty * 4 + 3][d];
            float b0 = Ks[tx * 2 + 0][d];
            float b1 = Ks[tx * 2 + 1][d];
            sv[0][0] += a0 * b0; sv[0][1] += a0 * b1;
            sv[1][0] += a1 * b0; sv[1][1] += a1 * b1;
            sv[2][0] += a2 * b0; sv[2][1] += a2 * b1;
            sv[3][0] += a3 * b0; sv[3][1] += a3 * b1;
        }
        #pragma unroll
        for (int i = 0; i < 4; i++)
            #pragma unroll
            for (int j = 0; j < 2; j++) {
                float x = sv[i][j] * scale;
                if (msk[tx * 2 + j] == 0) x = -3.0e38f;
                Ps[ty * 4 + i][tx * 2 + j] = x;
            }
        __syncthreads();

        if (tid < 64) {
            int r = tid;
            float m0 = rowm[r];
            float tm = m0;
            #pragma unroll
            for (int j = 0; j < 32; j++) tm = fmaxf(tm, Ps[r][j]);
            float c = __expf(m0 - tm);
            float l = rowl[r] * c;
            #pragma unroll
            for (int j = 0; j < 32; j++) {
                float p = __expf(Ps[r][j] - tm);
                Ps[r][j] = p;
                l += p;
            }
            rowm[r] = tm; rowl[r] = l; corr[r] = c;
        }
        __syncthreads();

        #pragma unroll
        for (int i = 0; i < 4; i++) {
            float c = corr[ty * 4 + i];
            #pragma unroll
            for (int j = 0; j < 4; j++) acc[i][j] *= c;
        }
        #pragma unroll
        for (int kk = 0; kk < 32; kk++) {
            float p0 = Ps[ty * 4 + 0][kk];
            float p1 = Ps[ty * 4 + 1][kk];
            float p2 = Ps[ty * 4 + 2][kk];
            float p3 = Ps[ty * 4 + 3][kk];
            float b0 = Vs[kk][tx * 4 + 0];
            float b1 = Vs[kk][tx * 4 + 1];
            float b2 = Vs[kk][tx * 4 + 2];
            float b3 = Vs[kk][tx * 4 + 3];
            acc[0][0] += p0 * b0; acc[0][1] += p0 * b1; acc[0][2] += p0 * b2; acc[0][3] += p0 * b3;
            acc[1][0] += p1 * b0; acc[1][1] += p1 * b1; acc[1][2] += p1 * b2; acc[1][3] += p1 * b3;
            acc[2][0] += p2 * b0; acc[2][1] += p2 * b1; acc[2][2] += p2 * b2; acc[2][3] += p2 * b3;
            acc[3][0] += p3 * b0; acc[3][1] += p3 * b1; acc[3][2] += p3 * b2; acc[3][3] += p3 * b3;
        }
        __syncthreads();
    }

    #pragma unroll
    for (int i = 0; i < 4; i++) {
        float inv = 1.0f / rowl[ty * 4 + i];
        #pragma unroll
        for (int j = 0; j < 4; j++)
            o[base_q + (size_t)(ty * 4 + i) * DIM + tx * 4 + j] = acc[i][j] * inv;
    }
}

// ---------------------------------------------------------------------------
// kernel_launch
// ---------------------------------------------------------------------------
extern "C" void kernel_launch(void* const* d_in, const int* in_sizes, int n_in,
                              void* d_out, int out_size)
{
    const float* H    = (const float*)d_in[0];
    const int*   mask = (const int*)  d_in[1];
    const float* Wq   = (const float*)d_in[2];
    const float* Wk   = (const float*)d_in[3];
    const float* Wv   = (const float*)d_in[4];
    const float* Wo   = (const float*)d_in[5];
    float* out = (float*)d_out;

    float *q, *k, *v, *ao, *wt;
    cudaGetSymbolAddress((void**)&q,  g_q);
    cudaGetSymbolAddress((void**)&k,  g_k);
    cudaGetSymbolAddress((void**)&v,  g_v);
    cudaGetSymbolAddress((void**)&ao, g_ao);
    cudaGetSymbolAddress((void**)&wt, g_wt);
    float* wtq = wt;
    float* wtk = wt + DIM * DIM;
    float* wtv = wt + 2 * DIM * DIM;
    float* wto = wt + 3 * DIM * DIM;

    cudaFuncSetAttribute(gemm_mma_kernel,
                         cudaFuncAttributeMaxDynamicSharedMemorySize, GEMM_SMEM);

    dim3 tb(32, 8), tg(DIM / 32, DIM / 32);
    transpose_kernel<<<tg, tb>>>(Wq, wtq);
    transpose_kernel<<<tg, tb>>>(Wk, wtk);
    transpose_kernel<<<tg, tb>>>(Wv, wtv);
    transpose_kernel<<<tg, tb>>>(Wo, wto);

    dim3 gg(DIM / BN, MROWS / BM);   // (8, 32)
    gemm_mma_kernel<<<gg, 256, GEMM_SMEM>>>(H, wtq, q);
    gemm_mma_kernel<<<gg, 256, GEMM_SMEM>>>(H, wtk, k);
    gemm_mma_kernel<<<gg, 256, GEMM_SMEM>>>(H, wtv, v);

    dim3 ga(SEQ / 64, HEADS, BATCH); // (32, 16, 2)
    attn_kernel<<<ga, 256>>>(q, k, v, mask, ao);

    gemm_mma_kernel<<<gg, 256, GEMM_SMEM>>>(ao, wto, out);
}

// round 4
// speedup vs baseline: 3.8827x; 2.2074x over previous
#include <cuda_runtime.h>
#include <cuda_bf16.h>
#include <cstdint>

// Problem constants
#define BATCH 2
#define SEQ   2048
#define DIM   1024
#define HEADS 16
#define HDIM  64
#define MROWS (BATCH*SEQ)   // 4096

// Scratch (allocation-free rule: __device__ globals)
__device__ float g_q [MROWS * DIM];
__device__ float g_k [MROWS * DIM];
__device__ float g_v [MROWS * DIM];
__device__ float g_ao[MROWS * DIM];
__device__ float g_wt[4 * DIM * DIM];   // transposed weights [N][K]

// ---------------------------------------------------------------------------
// helpers
// ---------------------------------------------------------------------------
__device__ __forceinline__ uint32_t smem_u32(const void* p) {
    uint32_t a;
    asm("{ .reg .u64 t; cvta.to.shared.u64 t, %1; cvt.u32.u64 %0, t; }"
        : "=r"(a) : "l"(p));
    return a;
}
__device__ __forceinline__ void cp16(uint32_t dst, const void* src) {
    asm volatile("cp.async.cg.shared.global [%0], [%1], 16;"
                 :: "r"(dst), "l"(src));
}
#define CP_COMMIT() asm volatile("cp.async.commit_group;" ::: "memory")
#define CP_WAIT1()  asm volatile("cp.async.wait_group 1;" ::: "memory")
#define CP_WAIT0()  asm volatile("cp.async.wait_group 0;" ::: "memory")

__device__ __forceinline__ uint32_t f2tf32(float f) {
    uint32_t r;
    asm("cvt.rna.tf32.f32 %0, %1;" : "=r"(r) : "f"(f));
    return r;
}
__device__ __forceinline__ void mma_tf32(float* c,
    uint32_t a0, uint32_t a1, uint32_t a2, uint32_t a3,
    uint32_t b0, uint32_t b1)
{
    asm volatile(
        "mma.sync.aligned.m16n8k8.row.col.f32.tf32.tf32.f32 "
        "{%0,%1,%2,%3}, {%4,%5,%6,%7}, {%8,%9}, {%0,%1,%2,%3};"
        : "+f"(c[0]), "+f"(c[1]), "+f"(c[2]), "+f"(c[3])
        : "r"(a0), "r"(a1), "r"(a2), "r"(a3), "r"(b0), "r"(b1));
}

// ---------------------------------------------------------------------------
// Weight transpose: WT[n][k] = W[k][n], 1024x1024
// ---------------------------------------------------------------------------
__global__ __launch_bounds__(256) void transpose_kernel(
    const float* __restrict__ W, float* __restrict__ WT)
{
    __shared__ float t[32][33];
    int bx = blockIdx.x * 32, by = blockIdx.y * 32;
    int x = bx + threadIdx.x;
    #pragma unroll
    for (int j = 0; j < 32; j += 8)
        t[threadIdx.y + j][threadIdx.x] = W[(size_t)(by + threadIdx.y + j) * DIM + x];
    __syncthreads();
    x = by + threadIdx.x;
    #pragma unroll
    for (int j = 0; j < 32; j += 8)
        WT[(size_t)(bx + threadIdx.y + j) * DIM + x] = t[threadIdx.x][threadIdx.y + j];
}

// ---------------------------------------------------------------------------
// mma.sync tf32 GEMM (unchanged from R3, passing): C = A @ BT^T
// ---------------------------------------------------------------------------
#define BM 128
#define BN 128
#define BK 32
#define GLDP 36
#define TILE_FLOATS (128 * GLDP)
#define STAGE_FLOATS (2 * TILE_FLOATS)
#define GEMM_SMEM (2 * STAGE_FLOATS * 4)
#define NCHUNK (DIM / BK)

__global__ __launch_bounds__(256, 2) void gemm_mma_kernel(
    const float* __restrict__ A, const float* __restrict__ BT,
    float* __restrict__ C)
{
    extern __shared__ float sm[];
    const uint32_t sbase = smem_u32(sm);
    const int tid = threadIdx.x;
    const int wid = tid >> 5;
    const int lid = tid & 31;
    const int wm  = wid >> 2;
    const int wn  = wid & 3;
    const int g   = lid >> 2;
    const int tg  = lid & 3;
    const int bm = blockIdx.y * BM;
    const int bn = blockIdx.x * BN;

    float acc[4][4][4] = {};

    auto load_chunk = [&](int c, int stg) {
        const float* Ag = A  + (size_t)bm * DIM + c * BK;
        const float* Bg = BT + (size_t)bn * DIM + c * BK;
        const uint32_t aB = sbase + (uint32_t)(stg * STAGE_FLOATS) * 4;
        const uint32_t bB = aB + TILE_FLOATS * 4;
        #pragma unroll
        for (int i = 0; i < 4; i++) {
            int idx = tid + i * 256;
            int r = idx >> 3, s = idx & 7;
            uint32_t off = (uint32_t)(r * GLDP + s * 4) * 4;
            cp16(aB + off, Ag + (size_t)r * DIM + s * 4);
            cp16(bB + off, Bg + (size_t)r * DIM + s * 4);
        }
    };

    auto compute = [&](int stg) {
        const float* As = sm + stg * STAGE_FLOATS;
        const float* Bs = As + TILE_FLOATS;
        #pragma unroll
        for (int kk = 0; kk < 4; kk++) {
            const int k0 = kk * 8;
            uint32_t af[4][4], bf[4][2];
            #pragma unroll
            for (int fm = 0; fm < 4; fm++) {
                const float* ar = As + (wm * 64 + fm * 16 + g) * GLDP + k0;
                af[fm][0] = f2tf32(ar[tg]);
                af[fm][1] = f2tf32(ar[8 * GLDP + tg]);
                af[fm][2] = f2tf32(ar[tg + 4]);
                af[fm][3] = f2tf32(ar[8 * GLDP + tg + 4]);
            }
            #pragma unroll
            for (int fn = 0; fn < 4; fn++) {
                const float* br = Bs + (wn * 32 + fn * 8 + g) * GLDP + k0;
                bf[fn][0] = f2tf32(br[tg]);
                bf[fn][1] = f2tf32(br[tg + 4]);
            }
            #pragma unroll
            for (int fm = 0; fm < 4; fm++)
                #pragma unroll
                for (int fn = 0; fn < 4; fn++)
                    mma_tf32(acc[fm][fn], af[fm][0], af[fm][1], af[fm][2], af[fm][3],
                             bf[fn][0], bf[fn][1]);
        }
    };

    load_chunk(0, 0); CP_COMMIT();
    for (int c = 0; c < NCHUNK; c++) {
        if (c + 1 < NCHUNK) { load_chunk(c + 1, (c + 1) & 1); CP_COMMIT(); }
        if (c + 1 < NCHUNK) { CP_WAIT1(); } else { CP_WAIT0(); }
        __syncthreads();
        compute(c & 1);
        __syncthreads();
    }

    #pragma unroll
    for (int fm = 0; fm < 4; fm++) {
        const int row = bm + wm * 64 + fm * 16 + g;
        #pragma unroll
        for (int fn = 0; fn < 4; fn++) {
            const int col = bn + wn * 32 + fn * 8 + tg * 2;
            float2 lo = make_float2(acc[fm][fn][0], acc[fm][fn][1]);
            float2 hi = make_float2(acc[fm][fn][2], acc[fm][fn][3]);
            *(float2*)(C + (size_t)row * DIM + col)       = lo;
            *(float2*)(C + (size_t)(row + 8) * DIM + col) = hi;
        }
    }
}

// ---------------------------------------------------------------------------
// Tensor-core flash attention (tf32 mma, fp32 softmax, online).
// CTA = (128 q-rows, head, batch). 8 warps x 16 rows. 64-key tiles, 32 iters.
// K smem pad 68 floats, V pad 72, P (warp-private) pad 68 — conflict-free frags.
// ---------------------------------------------------------------------------
#define AKEYS 64
#define ALDK 68
#define ALDV 72
#define ALDP 68
#define KS_OFF 0                       // 2 * 64*68 = 8704 floats
#define VS_OFF 8704                    // 2 * 64*72 = 9216 floats
#define PS_OFF 17920                   // 128*68    = 8704 floats
#define MSK_OFF 26624                  // 128 ints
#define ATT_SMEM ((26624 + 128) * 4)   // 107008 bytes
#define NKT (SEQ / AKEYS)              // 32

__global__ __launch_bounds__(256, 1) void attn_mma_kernel(
    const float* __restrict__ q, const float* __restrict__ k,
    const float* __restrict__ v, const int* __restrict__ mask,
    float* __restrict__ o)
{
    extern __shared__ float sA[];
    const uint32_t sbase = smem_u32(sA);
    float* Ks = sA + KS_OFF;
    float* Vs = sA + VS_OFF;
    float* Ps = sA + PS_OFF;
    uint32_t* PsU = (uint32_t*)Ps;
    int* Msk = (int*)(sA + MSK_OFF);

    const int b  = blockIdx.z;
    const int h  = blockIdx.y;
    const int qt = blockIdx.x;
    const int tid = threadIdx.x;
    const int w   = tid >> 5;
    const int lid = tid & 31;
    const int g   = lid >> 2;
    const int tg  = lid & 3;

    const int qr0 = w * 16 + g;        // warp-local rows (block frame)
    const int qr1 = qr0 + 8;

    // ---- stage Q tile (128x64) into Ps via cp.async ----
    const float* Qg = q + ((size_t)(b * SEQ + qt * 128)) * DIM + h * HDIM;
    {
        const uint32_t pB = sbase + PS_OFF * 4;
        #pragma unroll
        for (int i = 0; i < 8; i++) {
            int idx = tid + i * 256;          // 0..2047
            int r = idx >> 4, sg = idx & 15;
            cp16(pB + (uint32_t)(r * ALDP + sg * 4) * 4, Qg + (size_t)r * DIM + sg * 4);
        }
    }
    CP_COMMIT();

    // ---- KV tile loader: tile it -> stage st ----
    auto load_kv = [&](int it, int st) {
        const float* Kg = k + ((size_t)(b * SEQ + it * AKEYS)) * DIM + h * HDIM;
        const float* Vg = v + ((size_t)(b * SEQ + it * AKEYS)) * DIM + h * HDIM;
        const uint32_t kB = sbase + (uint32_t)(KS_OFF + st * AKEYS * ALDK) * 4;
        const uint32_t vB = sbase + (uint32_t)(VS_OFF + st * AKEYS * ALDV) * 4;
        #pragma unroll
        for (int i = 0; i < 4; i++) {
            int idx = tid + i * 256;          // 0..1023
            int r = idx >> 4, sg = idx & 15;
            cp16(kB + (uint32_t)(r * ALDK + sg * 4) * 4, Kg + (size_t)r * DIM + sg * 4);
            cp16(vB + (uint32_t)(r * ALDV + sg * 4) * 4, Vg + (size_t)r * DIM + sg * 4);
        }
        if (tid < 16)
            cp16(sbase + (uint32_t)(MSK_OFF + st * 64) * 4 + tid * 16,
                 mask + b * SEQ + it * AKEYS + tid * 4);
    };

    load_kv(0, 0); CP_COMMIT();
    CP_WAIT1();                // Q group done
    __syncthreads();

    // ---- preload Q fragments (scale folded in) ----
    uint32_t aq[8][4];
    #pragma unroll
    for (int ks = 0; ks < 8; ks++) {
        const float* qr = Ps + qr0 * ALDP + ks * 8;
        aq[ks][0] = f2tf32(0.125f * qr[tg]);
        aq[ks][1] = f2tf32(0.125f * qr[8 * ALDP + tg]);
        aq[ks][2] = f2tf32(0.125f * qr[tg + 4]);
        aq[ks][3] = f2tf32(0.125f * qr[8 * ALDP + tg + 4]);
    }

    float m0 = -3.0e38f, m1 = -3.0e38f, l0 = 0.0f, l1 = 0.0f;
    float oacc[8][4] = {};

    for (int it = 0; it < NKT; it++) {
        __syncthreads();                       // prev compute done with alt buffer
        if (it + 1 < NKT) { load_kv(it + 1, (it + 1) & 1); CP_COMMIT(); }
        if (it + 1 < NKT) { CP_WAIT1(); } else { CP_WAIT0(); }
        __syncthreads();

        const int st = it & 1;
        const float* Kt = Ks + st * AKEYS * ALDK;
        const float* Vt = Vs + st * AKEYS * ALDV;
        const int*   Mi = Msk + st * 64;

        // ---- S = Q @ K^T for 64 keys ----
        float sacc[8][4] = {};
        #pragma unroll
        for (int nt = 0; nt < 8; nt++) {
            const float* kr = Kt + (nt * 8 + g) * ALDK;
            #pragma unroll
            for (int ks = 0; ks < 8; ks++) {
                uint32_t b0 = f2tf32(kr[ks * 8 + tg]);
                uint32_t b1 = f2tf32(kr[ks * 8 + tg + 4]);
                mma_tf32(sacc[nt], aq[ks][0], aq[ks][1], aq[ks][2], aq[ks][3], b0, b1);
            }
        }

        // ---- mask ----
        #pragma unroll
        for (int nt = 0; nt < 8; nt++) {
            int c = nt * 8 + 2 * tg;
            if (Mi[c]     == 0) { sacc[nt][0] = -3.0e38f; sacc[nt][2] = -3.0e38f; }
            if (Mi[c + 1] == 0) { sacc[nt][1] = -3.0e38f; sacc[nt][3] = -3.0e38f; }
        }

        // ---- online softmax (quad-reduced) ----
        float tm0 = -3.0e38f, tm1 = -3.0e38f;
        #pragma unroll
        for (int nt = 0; nt < 8; nt++) {
            tm0 = fmaxf(tm0, fmaxf(sacc[nt][0], sacc[nt][1]));
            tm1 = fmaxf(tm1, fmaxf(sacc[nt][2], sacc[nt][3]));
        }
        tm0 = fmaxf(tm0, __shfl_xor_sync(0xffffffffu, tm0, 1));
        tm0 = fmaxf(tm0, __shfl_xor_sync(0xffffffffu, tm0, 2));
        tm1 = fmaxf(tm1, __shfl_xor_sync(0xffffffffu, tm1, 1));
        tm1 = fmaxf(tm1, __shfl_xor_sync(0xffffffffu, tm1, 2));

        float mn0 = fmaxf(m0, tm0), mn1 = fmaxf(m1, tm1);
        float corr0 = __expf(m0 - mn0), corr1 = __expf(m1 - mn1);
        m0 = mn0; m1 = mn1;

        float sum0 = 0.0f, sum1 = 0.0f;
        #pragma unroll
        for (int nt = 0; nt < 8; nt++) {
            float p0 = __expf(sacc[nt][0] - mn0);
            float p1 = __expf(sacc[nt][1] - mn0);
            float p2 = __expf(sacc[nt][2] - mn1);
            float p3 = __expf(sacc[nt][3] - mn1);
            sum0 += p0 + p1; sum1 += p2 + p3;
            int c = nt * 8 + 2 * tg;
            PsU[qr0 * ALDP + c]     = f2tf32(p0);
            PsU[qr0 * ALDP + c + 1] = f2tf32(p1);
            PsU[qr1 * ALDP + c]     = f2tf32(p2);
            PsU[qr1 * ALDP + c + 1] = f2tf32(p3);
        }
        sum0 += __shfl_xor_sync(0xffffffffu, sum0, 1);
        sum0 += __shfl_xor_sync(0xffffffffu, sum0, 2);
        sum1 += __shfl_xor_sync(0xffffffffu, sum1, 1);
        sum1 += __shfl_xor_sync(0xffffffffu, sum1, 2);
        l0 = l0 * corr0 + sum0;
        l1 = l1 * corr1 + sum1;

        // ---- rescale O ----
        #pragma unroll
        for (int dt = 0; dt < 8; dt++) {
            oacc[dt][0] *= corr0; oacc[dt][1] *= corr0;
            oacc[dt][2] *= corr1; oacc[dt][3] *= corr1;
        }
        __syncwarp();   // P stores visible across lanes of this warp

        // ---- O += P @ V ----
        #pragma unroll
        for (int kt = 0; kt < 8; kt++) {
            uint32_t a0 = PsU[qr0 * ALDP + kt * 8 + tg];
            uint32_t a1 = PsU[qr1 * ALDP + kt * 8 + tg];
            uint32_t a2 = PsU[qr0 * ALDP + kt * 8 + tg + 4];
            uint32_t a3 = PsU[qr1 * ALDP + kt * 8 + tg + 4];
            const float* vr0 = Vt + (kt * 8 + tg) * ALDV;
            const float* vr1 = Vt + (kt * 8 + tg + 4) * ALDV;
            #pragma unroll
            for (int dt = 0; dt < 8; dt++) {
                uint32_t b0 = f2tf32(vr0[dt * 8 + g]);
                uint32_t b1 = f2tf32(vr1[dt * 8 + g]);
                mma_tf32(oacc[dt], a0, a1, a2, a3, b0, b1);
            }
        }
        __syncwarp();   // P reads done before next iter's stores
    }

    // ---- epilogue ----
    const float inv0 = 1.0f / l0, inv1 = 1.0f / l1;
    float* Og = o + ((size_t)(b * SEQ + qt * 128)) * DIM + h * HDIM;
    #pragma unroll
    for (int dt = 0; dt < 8; dt++) {
        int c = dt * 8 + 2 * tg;
        *(float2*)(Og + (size_t)qr0 * DIM + c) =
            make_float2(oacc[dt][0] * inv0, oacc[dt][1] * inv0);
        *(float2*)(Og + (size_t)qr1 * DIM + c) =
            make_float2(oacc[dt][2] * inv1, oacc[dt][3] * inv1);
    }
}

// ---------------------------------------------------------------------------
// kernel_launch
// ---------------------------------------------------------------------------
extern "C" void kernel_launch(void* const* d_in, const int* in_sizes, int n_in,
                              void* d_out, int out_size)
{
    const float* H    = (const float*)d_in[0];
    const int*   mask = (const int*)  d_in[1];
    const float* Wq   = (const float*)d_in[2];
    const float* Wk   = (const float*)d_in[3];
    const float* Wv   = (const float*)d_in[4];
    const float* Wo   = (const float*)d_in[5];
    float* out = (float*)d_out;

    float *q, *k, *v, *ao, *wt;
    cudaGetSymbolAddress((void**)&q,  g_q);
    cudaGetSymbolAddress((void**)&k,  g_k);
    cudaGetSymbolAddress((void**)&v,  g_v);
    cudaGetSymbolAddress((void**)&ao, g_ao);
    cudaGetSymbolAddress((void**)&wt, g_wt);
    float* wtq = wt;
    float* wtk = wt + DIM * DIM;
    float* wtv = wt + 2 * DIM * DIM;
    float* wto = wt + 3 * DIM * DIM;

    cudaFuncSetAttribute(gemm_mma_kernel,
                         cudaFuncAttributeMaxDynamicSharedMemorySize, GEMM_SMEM);
    cudaFuncSetAttribute(attn_mma_kernel,
                         cudaFuncAttributeMaxDynamicSharedMemorySize, ATT_SMEM);

    dim3 tb(32, 8), tg(DIM / 32, DIM / 32);
    transpose_kernel<<<tg, tb>>>(Wq, wtq);
    transpose_kernel<<<tg, tb>>>(Wk, wtk);
    transpose_kernel<<<tg, tb>>>(Wv, wtv);
    transpose_kernel<<<tg, tb>>>(Wo, wto);

    dim3 gg(DIM / BN, MROWS / BM);   // (8, 32)
    gemm_mma_kernel<<<gg, 256, GEMM_SMEM>>>(H, wtq, q);
    gemm_mma_kernel<<<gg, 256, GEMM_SMEM>>>(H, wtk, k);
    gemm_mma_kernel<<<gg, 256, GEMM_SMEM>>>(H, wtv, v);

    dim3 ga(SEQ / 128, HEADS, BATCH); // (16, 16, 2)
    attn_mma_kernel<<<ga, 256, ATT_SMEM>>>(q, k, v, mask, ao);

    gemm_mma_kernel<<<gg, 256, GEMM_SMEM>>>(ao, wto, out);
}

// round 5
// speedup vs baseline: 4.5902x; 1.1822x over previous
#include <cuda_runtime.h>
#include <cuda_bf16.h>
#include <cstdint>

// Problem constants
#define BATCH 2
#define SEQ   2048
#define DIM   1024
#define HEADS 16
#define HDIM  64
#define MROWS (BATCH*SEQ)   // 4096
#define QKVLD (3*DIM)       // 3072

// Scratch (allocation-free rule: __device__ globals)
__device__ float g_qkv[MROWS * QKVLD];  // fused Q|K|V, row stride 3072
__device__ float g_ao [MROWS * DIM];
__device__ float g_wt [4 * DIM * DIM];  // WqT|WkT|WvT|WoT, each [N][K]

// ---------------------------------------------------------------------------
// helpers
// ---------------------------------------------------------------------------
__device__ __forceinline__ uint32_t smem_u32(const void* p) {
    uint32_t a;
    asm("{ .reg .u64 t; cvta.to.shared.u64 t, %1; cvt.u32.u64 %0, t; }"
        : "=r"(a) : "l"(p));
    return a;
}
__device__ __forceinline__ void cp16(uint32_t dst, const void* src) {
    asm volatile("cp.async.cg.shared.global [%0], [%1], 16;"
                 :: "r"(dst), "l"(src));
}
#define CP_COMMIT() asm volatile("cp.async.commit_group;" ::: "memory")
#define CP_WAIT1()  asm volatile("cp.async.wait_group 1;" ::: "memory")
#define CP_WAIT0()  asm volatile("cp.async.wait_group 0;" ::: "memory")

__device__ __forceinline__ uint32_t f2tf32(float f) {
    uint32_t r;
    asm("cvt.rna.tf32.f32 %0, %1;" : "=r"(r) : "f"(f));
    return r;
}
__device__ __forceinline__ void mma_tf32(float* c,
    uint32_t a0, uint32_t a1, uint32_t a2, uint32_t a3,
    uint32_t b0, uint32_t b1)
{
    asm volatile(
        "mma.sync.aligned.m16n8k8.row.col.f32.tf32.tf32.f32 "
        "{%0,%1,%2,%3}, {%4,%5,%6,%7}, {%8,%9}, {%0,%1,%2,%3};"
        : "+f"(c[0]), "+f"(c[1]), "+f"(c[2]), "+f"(c[3])
        : "r"(a0), "r"(a1), "r"(a2), "r"(a3), "r"(b0), "r"(b1));
}

// ---------------------------------------------------------------------------
// Fused weight transpose: 4 weights in one launch (grid.z selects source).
// ---------------------------------------------------------------------------
__global__ __launch_bounds__(256) void transpose4_kernel(
    const float* __restrict__ W0, const float* __restrict__ W1,
    const float* __restrict__ W2, const float* __restrict__ W3,
    float* __restrict__ WT)
{
    __shared__ float t[32][33];
    const float* W = (blockIdx.z == 0) ? W0 : (blockIdx.z == 1) ? W1
                   : (blockIdx.z == 2) ? W2 : W3;
    float* D = WT + (size_t)blockIdx.z * DIM * DIM;
    int bx = blockIdx.x * 32, by = blockIdx.y * 32;
    int x = bx + threadIdx.x;
    #pragma unroll
    for (int j = 0; j < 32; j += 8)
        t[threadIdx.y + j][threadIdx.x] = W[(size_t)(by + threadIdx.y + j) * DIM + x];
    __syncthreads();
    x = by + threadIdx.x;
    #pragma unroll
    for (int j = 0; j < 32; j += 8)
        D[(size_t)(bx + threadIdx.y + j) * DIM + x] = t[threadIdx.x][threadIdx.y + j];
}

// ---------------------------------------------------------------------------
// mma.sync tf32 GEMM: C[4096, N_out] = A[4096,1024] @ BT[N_out,1024]^T
// RND: epilogue stores tf32-rounded bit patterns (for QKV feeding attention).
// ---------------------------------------------------------------------------
#define BM 128
#define BN 128
#define BK 32
#define GLDP 36
#define TILE_FLOATS (128 * GLDP)
#define STAGE_FLOATS (2 * TILE_FLOATS)
#define GEMM_SMEM (2 * STAGE_FLOATS * 4)
#define NCHUNK (DIM / BK)

template<bool RND>
__global__ __launch_bounds__(256, 2) void gemm_mma_kernel(
    const float* __restrict__ A, const float* __restrict__ BT,
    float* __restrict__ C, int ldc)
{
    extern __shared__ float sm[];
    const uint32_t sbase = smem_u32(sm);
    const int tid = threadIdx.x;
    const int wid = tid >> 5;
    const int lid = tid & 31;
    const int wm  = wid >> 2;
    const int wn  = wid & 3;
    const int g   = lid >> 2;
    const int tg  = lid & 3;
    const int bm = blockIdx.y * BM;
    const int bn = blockIdx.x * BN;

    float acc[4][4][4] = {};

    auto load_chunk = [&](int c, int stg) {
        const float* Ag = A  + (size_t)bm * DIM + c * BK;
        const float* Bg = BT + (size_t)bn * DIM + c * BK;
        const uint32_t aB = sbase + (uint32_t)(stg * STAGE_FLOATS) * 4;
        const uint32_t bB = aB + TILE_FLOATS * 4;
        #pragma unroll
        for (int i = 0; i < 4; i++) {
            int idx = tid + i * 256;
            int r = idx >> 3, s = idx & 7;
            uint32_t off = (uint32_t)(r * GLDP + s * 4) * 4;
            cp16(aB + off, Ag + (size_t)r * DIM + s * 4);
            cp16(bB + off, Bg + (size_t)r * DIM + s * 4);
        }
    };

    auto compute = [&](int stg) {
        const float* As = sm + stg * STAGE_FLOATS;
        const float* Bs = As + TILE_FLOATS;
        #pragma unroll
        for (int kk = 0; kk < 4; kk++) {
            const int k0 = kk * 8;
            uint32_t af[4][4], bf[4][2];
            #pragma unroll
            for (int fm = 0; fm < 4; fm++) {
                const float* ar = As + (wm * 64 + fm * 16 + g) * GLDP + k0;
                af[fm][0] = f2tf32(ar[tg]);
                af[fm][1] = f2tf32(ar[8 * GLDP + tg]);
                af[fm][2] = f2tf32(ar[tg + 4]);
                af[fm][3] = f2tf32(ar[8 * GLDP + tg + 4]);
            }
            #pragma unroll
            for (int fn = 0; fn < 4; fn++) {
                const float* br = Bs + (wn * 32 + fn * 8 + g) * GLDP + k0;
                bf[fn][0] = f2tf32(br[tg]);
                bf[fn][1] = f2tf32(br[tg + 4]);
            }
            #pragma unroll
            for (int fm = 0; fm < 4; fm++)
                #pragma unroll
                for (int fn = 0; fn < 4; fn++)
                    mma_tf32(acc[fm][fn], af[fm][0], af[fm][1], af[fm][2], af[fm][3],
                             bf[fn][0], bf[fn][1]);
        }
    };

    load_chunk(0, 0); CP_COMMIT();
    for (int c = 0; c < NCHUNK; c++) {
        if (c + 1 < NCHUNK) { load_chunk(c + 1, (c + 1) & 1); CP_COMMIT(); }
        if (c + 1 < NCHUNK) { CP_WAIT1(); } else { CP_WAIT0(); }
        __syncthreads();
        compute(c & 1);
        __syncthreads();
    }

    #pragma unroll
    for (int fm = 0; fm < 4; fm++) {
        const int row = bm + wm * 64 + fm * 16 + g;
        #pragma unroll
        for (int fn = 0; fn < 4; fn++) {
            const int col = bn + wn * 32 + fn * 8 + tg * 2;
            float2 lo, hi;
            if (RND) {
                lo.x = __uint_as_float(f2tf32(acc[fm][fn][0]));
                lo.y = __uint_as_float(f2tf32(acc[fm][fn][1]));
                hi.x = __uint_as_float(f2tf32(acc[fm][fn][2]));
                hi.y = __uint_as_float(f2tf32(acc[fm][fn][3]));
            } else {
                lo = make_float2(acc[fm][fn][0], acc[fm][fn][1]);
                hi = make_float2(acc[fm][fn][2], acc[fm][fn][3]);
            }
            *(float2*)(C + (size_t)row * ldc + col)       = lo;
            *(float2*)(C + (size_t)(row + 8) * ldc + col) = hi;
        }
    }
}

// ---------------------------------------------------------------------------
// Tensor-core flash attention (tf32 mma, fp32 softmax in base-2, online).
// Inputs PRE-ROUNDED to tf32 -> no cvt in mainloop; K/V frags loaded as uint.
// CTA = (128 q-rows, head, batch). 8 warps x 16 rows. 64-key tiles, 32 iters.
// ---------------------------------------------------------------------------
#define AKEYS 64
#define ALDK 68
#define ALDV 72
#define ALDP 68
#define KS_OFF 0                       // 2 * 64*68 = 8704 floats
#define VS_OFF 8704                    // 2 * 64*72 = 9216 floats
#define PS_OFF 17920                   // 128*68    = 8704 floats
#define MSK_OFF 26624                  // 128 ints
#define ATT_SMEM ((26624 + 128) * 4)   // 107008 bytes
#define NKT (SEQ / AKEYS)              // 32
#define QSCALE2 0.18033688011112042f   // 0.125 * log2(e)

__global__ __launch_bounds__(256, 2) void attn_mma_kernel(
    const float* __restrict__ qkv, const int* __restrict__ mask,
    float* __restrict__ o)
{
    extern __shared__ float sA[];
    const uint32_t sbase = smem_u32(sA);
    float* Ps = sA + PS_OFF;
    uint32_t* PsU = (uint32_t*)Ps;
    const uint32_t* KsU = (const uint32_t*)(sA + KS_OFF);
    const uint32_t* VsU = (const uint32_t*)(sA + VS_OFF);
    int* Msk = (int*)(sA + MSK_OFF);

    const int b  = blockIdx.z;
    const int h  = blockIdx.y;
    const int qt = blockIdx.x;
    const int tid = threadIdx.x;
    const int w   = tid >> 5;
    const int lid = tid & 31;
    const int g   = lid >> 2;
    const int tg  = lid & 3;

    const int qr0 = w * 16 + g;
    const int qr1 = qr0 + 8;

    // ---- stage Q tile (128x64) into Ps via cp.async ----
    const float* Qg = qkv + ((size_t)(b * SEQ + qt * 128)) * QKVLD + h * HDIM;
    {
        const uint32_t pB = sbase + PS_OFF * 4;
        #pragma unroll
        for (int i = 0; i < 8; i++) {
            int idx = tid + i * 256;
            int r = idx >> 4, sg = idx & 15;
            cp16(pB + (uint32_t)(r * ALDP + sg * 4) * 4, Qg + (size_t)r * QKVLD + sg * 4);
        }
    }
    CP_COMMIT();

    // ---- KV tile loader ----
    auto load_kv = [&](int it, int st) {
        const float* Kg = qkv + ((size_t)(b * SEQ + it * AKEYS)) * QKVLD + DIM   + h * HDIM;
        const float* Vg = qkv + ((size_t)(b * SEQ + it * AKEYS)) * QKVLD + 2*DIM + h * HDIM;
        const uint32_t kB = sbase + (uint32_t)(KS_OFF + st * AKEYS * ALDK) * 4;
        const uint32_t vB = sbase + (uint32_t)(VS_OFF + st * AKEYS * ALDV) * 4;
        #pragma unroll
        for (int i = 0; i < 4; i++) {
            int idx = tid + i * 256;
            int r = idx >> 4, sg = idx & 15;
            cp16(kB + (uint32_t)(r * ALDK + sg * 4) * 4, Kg + (size_t)r * QKVLD + sg * 4);
            cp16(vB + (uint32_t)(r * ALDV + sg * 4) * 4, Vg + (size_t)r * QKVLD + sg * 4);
        }
        if (tid < 16)
            cp16(sbase + (uint32_t)(MSK_OFF + st * 64) * 4 + tid * 16,
                 mask + b * SEQ + it * AKEYS + tid * 4);
    };

    load_kv(0, 0); CP_COMMIT();
    CP_WAIT1();                // Q group done
    __syncthreads();

    // ---- preload Q fragments (base-2 scale folded; inputs pre-rounded) ----
    uint32_t aq[8][4];
    #pragma unroll
    for (int ks = 0; ks < 8; ks++) {
        const float* qr = Ps + qr0 * ALDP + ks * 8;
        aq[ks][0] = f2tf32(QSCALE2 * qr[tg]);
        aq[ks][1] = f2tf32(QSCALE2 * qr[8 * ALDP + tg]);
        aq[ks][2] = f2tf32(QSCALE2 * qr[tg + 4]);
        aq[ks][3] = f2tf32(QSCALE2 * qr[8 * ALDP + tg + 4]);
    }

    float m0 = -3.0e38f, m1 = -3.0e38f, l0 = 0.0f, l1 = 0.0f;
    float oacc[8][4] = {};

    for (int it = 0; it < NKT; it++) {
        __syncthreads();
        if (it + 1 < NKT) { load_kv(it + 1, (it + 1) & 1); CP_COMMIT(); }
        if (it + 1 < NKT) { CP_WAIT1(); } else { CP_WAIT0(); }
        __syncthreads();

        const int st = it & 1;
        const uint32_t* Kt = KsU + st * AKEYS * ALDK;
        const uint32_t* Vt = VsU + st * AKEYS * ALDV;
        const int*      Mi = Msk + st * 64;

        // ---- S = Q @ K^T (scores in log2 units) ----
        float sacc[8][4] = {};
        #pragma unroll
        for (int nt = 0; nt < 8; nt++) {
            const uint32_t* kr = Kt + (nt * 8 + g) * ALDK;
            #pragma unroll
            for (int ks = 0; ks < 8; ks++) {
                uint32_t b0 = kr[ks * 8 + tg];
                uint32_t b1 = kr[ks * 8 + tg + 4];
                mma_tf32(sacc[nt], aq[ks][0], aq[ks][1], aq[ks][2], aq[ks][3], b0, b1);
            }
        }

        // ---- mask ----
        #pragma unroll
        for (int nt = 0; nt < 8; nt++) {
            int c = nt * 8 + 2 * tg;
            if (Mi[c]     == 0) { sacc[nt][0] = -3.0e38f; sacc[nt][2] = -3.0e38f; }
            if (Mi[c + 1] == 0) { sacc[nt][1] = -3.0e38f; sacc[nt][3] = -3.0e38f; }
        }

        // ---- online softmax (base-2, quad-reduced) ----
        float tm0 = -3.0e38f, tm1 = -3.0e38f;
        #pragma unroll
        for (int nt = 0; nt < 8; nt++) {
            tm0 = fmaxf(tm0, fmaxf(sacc[nt][0], sacc[nt][1]));
            tm1 = fmaxf(tm1, fmaxf(sacc[nt][2], sacc[nt][3]));
        }
        tm0 = fmaxf(tm0, __shfl_xor_sync(0xffffffffu, tm0, 1));
        tm0 = fmaxf(tm0, __shfl_xor_sync(0xffffffffu, tm0, 2));
        tm1 = fmaxf(tm1, __shfl_xor_sync(0xffffffffu, tm1, 1));
        tm1 = fmaxf(tm1, __shfl_xor_sync(0xffffffffu, tm1, 2));

        float mn0 = fmaxf(m0, tm0), mn1 = fmaxf(m1, tm1);
        float corr0 = exp2f(m0 - mn0), corr1 = exp2f(m1 - mn1);
        m0 = mn0; m1 = mn1;

        float sum0 = 0.0f, sum1 = 0.0f;
        #pragma unroll
        for (int nt = 0; nt < 8; nt++) {
            float p0 = exp2f(sacc[nt][0] - mn0);
            float p1 = exp2f(sacc[nt][1] - mn0);
            float p2 = exp2f(sacc[nt][2] - mn1);
            float p3 = exp2f(sacc[nt][3] - mn1);
            sum0 += p0 + p1; sum1 += p2 + p3;
            int c = nt * 8 + 2 * tg;
            PsU[qr0 * ALDP + c]     = f2tf32(p0);
            PsU[qr0 * ALDP + c + 1] = f2tf32(p1);
            PsU[qr1 * ALDP + c]     = f2tf32(p2);
            PsU[qr1 * ALDP + c + 1] = f2tf32(p3);
        }
        sum0 += __shfl_xor_sync(0xffffffffu, sum0, 1);
        sum0 += __shfl_xor_sync(0xffffffffu, sum0, 2);
        sum1 += __shfl_xor_sync(0xffffffffu, sum1, 1);
        sum1 += __shfl_xor_sync(0xffffffffu, sum1, 2);
        l0 = l0 * corr0 + sum0;
        l1 = l1 * corr1 + sum1;

        // ---- rescale O ----
        #pragma unroll
        for (int dt = 0; dt < 8; dt++) {
            oacc[dt][0] *= corr0; oacc[dt][1] *= corr0;
            oacc[dt][2] *= corr1; oacc[dt][3] *= corr1;
        }
        __syncwarp();

        // ---- O += P @ V ----
        #pragma unroll
        for (int kt = 0; kt < 8; kt++) {
            uint32_t a0 = PsU[qr0 * ALDP + kt * 8 + tg];
            uint32_t a1 = PsU[qr1 * ALDP + kt * 8 + tg];
            uint32_t a2 = PsU[qr0 * ALDP + kt * 8 + tg + 4];
            uint32_t a3 = PsU[qr1 * ALDP + kt * 8 + tg + 4];
            const uint32_t* vr0 = Vt + (kt * 8 + tg) * ALDV;
            const uint32_t* vr1 = Vt + (kt * 8 + tg + 4) * ALDV;
            #pragma unroll
            for (int dt = 0; dt < 8; dt++) {
                mma_tf32(oacc[dt], a0, a1, a2, a3, vr0[dt * 8 + g], vr1[dt * 8 + g]);
            }
        }
        __syncwarp();
    }

    // ---- epilogue ----
    const float inv0 = 1.0f / l0, inv1 = 1.0f / l1;
    float* Og = o + ((size_t)(b * SEQ + qt * 128)) * DIM + h * HDIM;
    #pragma unroll
    for (int dt = 0; dt < 8; dt++) {
        int c = dt * 8 + 2 * tg;
        *(float2*)(Og + (size_t)qr0 * DIM + c) =
            make_float2(oacc[dt][0] * inv0, oacc[dt][1] * inv0);
        *(float2*)(Og + (size_t)qr1 * DIM + c) =
            make_float2(oacc[dt][2] * inv1, oacc[dt][3] * inv1);
    }
}

// ---------------------------------------------------------------------------
// kernel_launch
// ---------------------------------------------------------------------------
extern "C" void kernel_launch(void* const* d_in, const int* in_sizes, int n_in,
                              void* d_out, int out_size)
{
    const float* H    = (const float*)d_in[0];
    const int*   mask = (const int*)  d_in[1];
    const float* Wq   = (const float*)d_in[2];
    const float* Wk   = (const float*)d_in[3];
    const float* Wv   = (const float*)d_in[4];
    const float* Wo   = (const float*)d_in[5];
    float* out = (float*)d_out;

    float *qkv, *ao, *wt;
    cudaGetSymbolAddress((void**)&qkv, g_qkv);
    cudaGetSymbolAddress((void**)&ao,  g_ao);
    cudaGetSymbolAddress((void**)&wt,  g_wt);
    float* wto = wt + 3 * DIM * DIM;

    cudaFuncSetAttribute(gemm_mma_kernel<true>,
                         cudaFuncAttributeMaxDynamicSharedMemorySize, GEMM_SMEM);
    cudaFuncSetAttribute(gemm_mma_kernel<false>,
                         cudaFuncAttributeMaxDynamicSharedMemorySize, GEMM_SMEM);
    cudaFuncSetAttribute(attn_mma_kernel,
                         cudaFuncAttributeMaxDynamicSharedMemorySize, ATT_SMEM);

    dim3 tb(32, 8), tg(DIM / 32, DIM / 32, 4);
    transpose4_kernel<<<tg, tb>>>(Wq, Wk, Wv, Wo, wt);

    // Fused QKV projection: [4096, 3072], rounded-to-tf32 outputs
    dim3 gqkv(QKVLD / BN, MROWS / BM);   // (24, 32)
    gemm_mma_kernel<true><<<gqkv, 256, GEMM_SMEM>>>(H, wt, qkv, QKVLD);

    dim3 ga(SEQ / 128, HEADS, BATCH);    // (16, 16, 2)
    attn_mma_kernel<<<ga, 256, ATT_SMEM>>>(qkv, mask, ao);

    dim3 go(DIM / BN, MROWS / BM);       // (8, 32)
    gemm_mma_kernel<false><<<go, 256, GEMM_SMEM>>>(ao, wto, out, DIM);
}

// round 6
// speedup vs baseline: 4.6266x; 1.0079x over previous
#include <cuda_runtime.h>
#include <cuda_bf16.h>
#include <cstdint>

// Problem constants
#define BATCH 2
#define SEQ   2048
#define DIM   1024
#define HEADS 16
#define HDIM  64
#define MROWS (BATCH*SEQ)   // 4096
#define QKVLD (3*DIM)       // 3072

// Scratch (allocation-free rule: __device__ globals)
__device__ float g_qkv[MROWS * QKVLD];  // fused Q|K|V (tf32 bits), row stride 3072
__device__ float g_ao [MROWS * DIM];    // attention out (tf32 bits)
__device__ float g_hr [MROWS * DIM];    // H pre-rounded to tf32 bits
__device__ float g_wt [4 * DIM * DIM];  // WqT|WkT|WvT|WoT, transposed + tf32 bits

// ---------------------------------------------------------------------------
// helpers
// ---------------------------------------------------------------------------
__device__ __forceinline__ uint32_t smem_u32(const void* p) {
    uint32_t a;
    asm("{ .reg .u64 t; cvta.to.shared.u64 t, %1; cvt.u32.u64 %0, t; }"
        : "=r"(a) : "l"(p));
    return a;
}
__device__ __forceinline__ void cp16(uint32_t dst, const void* src) {
    asm volatile("cp.async.cg.shared.global [%0], [%1], 16;"
                 :: "r"(dst), "l"(src));
}
#define CP_COMMIT() asm volatile("cp.async.commit_group;" ::: "memory")
#define CP_WAIT1()  asm volatile("cp.async.wait_group 1;" ::: "memory")
#define CP_WAIT0()  asm volatile("cp.async.wait_group 0;" ::: "memory")

__device__ __forceinline__ uint32_t f2tf32(float f) {
    uint32_t r;
    asm("cvt.rna.tf32.f32 %0, %1;" : "=r"(r) : "f"(f));
    return r;
}
__device__ __forceinline__ void mma_tf32(float* c,
    uint32_t a0, uint32_t a1, uint32_t a2, uint32_t a3,
    uint32_t b0, uint32_t b1)
{
    asm volatile(
        "mma.sync.aligned.m16n8k8.row.col.f32.tf32.tf32.f32 "
        "{%0,%1,%2,%3}, {%4,%5,%6,%7}, {%8,%9}, {%0,%1,%2,%3};"
        : "+f"(c[0]), "+f"(c[1]), "+f"(c[2]), "+f"(c[3])
        : "r"(a0), "r"(a1), "r"(a2), "r"(a3), "r"(b0), "r"(b1));
}

// ---------------------------------------------------------------------------
// Elementwise tf32 pre-round: dst = round_tf32(src), float4 vectorized.
// ---------------------------------------------------------------------------
__global__ __launch_bounds__(256) void round_tf32_kernel(
    const float4* __restrict__ src, float4* __restrict__ dst, int n4)
{
    int i = blockIdx.x * 256 + threadIdx.x;
    if (i < n4) {
        float4 v = src[i];
        v.x = __uint_as_float(f2tf32(v.x));
        v.y = __uint_as_float(f2tf32(v.y));
        v.z = __uint_as_float(f2tf32(v.z));
        v.w = __uint_as_float(f2tf32(v.w));
        dst[i] = v;
    }
}

// ---------------------------------------------------------------------------
// Fused weight transpose + tf32 round: 4 weights in one launch.
// ---------------------------------------------------------------------------
__global__ __launch_bounds__(256) void transpose4_kernel(
    const float* __restrict__ W0, const float* __restrict__ W1,
    const float* __restrict__ W2, const float* __restrict__ W3,
    float* __restrict__ WT)
{
    __shared__ float t[32][33];
    const float* W = (blockIdx.z == 0) ? W0 : (blockIdx.z == 1) ? W1
                   : (blockIdx.z == 2) ? W2 : W3;
    float* D = WT + (size_t)blockIdx.z * DIM * DIM;
    int bx = blockIdx.x * 32, by = blockIdx.y * 32;
    int x = bx + threadIdx.x;
    #pragma unroll
    for (int j = 0; j < 32; j += 8)
        t[threadIdx.y + j][threadIdx.x] = W[(size_t)(by + threadIdx.y + j) * DIM + x];
    __syncthreads();
    x = by + threadIdx.x;
    #pragma unroll
    for (int j = 0; j < 32; j += 8)
        D[(size_t)(bx + threadIdx.y + j) * DIM + x] =
            __uint_as_float(f2tf32(t[threadIdx.x][threadIdx.y + j]));
}

// ---------------------------------------------------------------------------
// mma.sync tf32 GEMM, operands PRE-ROUNDED (no cvt in mainloop):
//   C[4096, N_out] = A[4096,1024] @ BT[N_out,1024]^T
// RND: epilogue stores tf32-rounded bits (for QKV feeding attention).
// ---------------------------------------------------------------------------
#define BM 128
#define BN 128
#define BK 32
#define GLDP 36
#define TILE_FLOATS (128 * GLDP)
#define STAGE_FLOATS (2 * TILE_FLOATS)
#define GEMM_SMEM (2 * STAGE_FLOATS * 4)
#define NCHUNK (DIM / BK)

template<bool RND>
__global__ __launch_bounds__(256, 2) void gemm_mma_kernel(
    const float* __restrict__ A, const float* __restrict__ BT,
    float* __restrict__ C, int ldc)
{
    extern __shared__ float sm[];
    const uint32_t sbase = smem_u32(sm);
    const uint32_t* smU = (const uint32_t*)sm;
    const int tid = threadIdx.x;
    const int wid = tid >> 5;
    const int lid = tid & 31;
    const int wm  = wid >> 2;
    const int wn  = wid & 3;
    const int g   = lid >> 2;
    const int tg  = lid & 3;
    const int bm = blockIdx.y * BM;
    const int bn = blockIdx.x * BN;

    float acc[4][4][4] = {};

    auto load_chunk = [&](int c, int stg) {
        const float* Ag = A  + (size_t)bm * DIM + c * BK;
        const float* Bg = BT + (size_t)bn * DIM + c * BK;
        const uint32_t aB = sbase + (uint32_t)(stg * STAGE_FLOATS) * 4;
        const uint32_t bB = aB + TILE_FLOATS * 4;
        #pragma unroll
        for (int i = 0; i < 4; i++) {
            int idx = tid + i * 256;
            int r = idx >> 3, s = idx & 7;
            uint32_t off = (uint32_t)(r * GLDP + s * 4) * 4;
            cp16(aB + off, Ag + (size_t)r * DIM + s * 4);
            cp16(bB + off, Bg + (size_t)r * DIM + s * 4);
        }
    };

    auto compute = [&](int stg) {
        const uint32_t* As = smU + stg * STAGE_FLOATS;
        const uint32_t* Bs = As + TILE_FLOATS;
        #pragma unroll
        for (int kk = 0; kk < 4; kk++) {
            const int k0 = kk * 8;
            uint32_t af[4][4], bf[4][2];
            #pragma unroll
            for (int fm = 0; fm < 4; fm++) {
                const uint32_t* ar = As + (wm * 64 + fm * 16 + g) * GLDP + k0;
                af[fm][0] = ar[tg];
                af[fm][1] = ar[8 * GLDP + tg];
                af[fm][2] = ar[tg + 4];
                af[fm][3] = ar[8 * GLDP + tg + 4];
            }
            #pragma unroll
            for (int fn = 0; fn < 4; fn++) {
                const uint32_t* br = Bs + (wn * 32 + fn * 8 + g) * GLDP + k0;
                bf[fn][0] = br[tg];
                bf[fn][1] = br[tg + 4];
            }
            #pragma unroll
            for (int fm = 0; fm < 4; fm++)
                #pragma unroll
                for (int fn = 0; fn < 4; fn++)
                    mma_tf32(acc[fm][fn], af[fm][0], af[fm][1], af[fm][2], af[fm][3],
                             bf[fn][0], bf[fn][1]);
        }
    };

    load_chunk(0, 0); CP_COMMIT();
    for (int c = 0; c < NCHUNK; c++) {
        if (c + 1 < NCHUNK) { load_chunk(c + 1, (c + 1) & 1); CP_COMMIT(); }
        if (c + 1 < NCHUNK) { CP_WAIT1(); } else { CP_WAIT0(); }
        __syncthreads();
        compute(c & 1);
        __syncthreads();
    }

    #pragma unroll
    for (int fm = 0; fm < 4; fm++) {
        const int row = bm + wm * 64 + fm * 16 + g;
        #pragma unroll
        for (int fn = 0; fn < 4; fn++) {
            const int col = bn + wn * 32 + fn * 8 + tg * 2;
            float2 lo, hi;
            if (RND) {
                lo.x = __uint_as_float(f2tf32(acc[fm][fn][0]));
                lo.y = __uint_as_float(f2tf32(acc[fm][fn][1]));
                hi.x = __uint_as_float(f2tf32(acc[fm][fn][2]));
                hi.y = __uint_as_float(f2tf32(acc[fm][fn][3]));
            } else {
                lo = make_float2(acc[fm][fn][0], acc[fm][fn][1]);
                hi = make_float2(acc[fm][fn][2], acc[fm][fn][3]);
            }
            *(float2*)(C + (size_t)row * ldc + col)       = lo;
            *(float2*)(C + (size_t)(row + 8) * ldc + col) = hi;
        }
    }
}

// ---------------------------------------------------------------------------
// Tensor-core flash attention (tf32 mma, fp32 softmax in base-2, online).
// Inputs PRE-ROUNDED to tf32 -> no cvt on K/V path; epilogue writes tf32 bits.
// CTA = (128 q-rows, head, batch). 8 warps x 16 rows. 64-key tiles, 32 iters.
// ---------------------------------------------------------------------------
#define AKEYS 64
#define ALDK 68
#define ALDV 72
#define ALDP 68
#define KS_OFF 0                       // 2 * 64*68 = 8704 floats
#define VS_OFF 8704                    // 2 * 64*72 = 9216 floats
#define PS_OFF 17920                   // 128*68    = 8704 floats
#define MSK_OFF 26624                  // 128 ints
#define ATT_SMEM ((26624 + 128) * 4)   // 107008 bytes
#define NKT (SEQ / AKEYS)              // 32
#define QSCALE2 0.18033688011112042f   // 0.125 * log2(e)

__global__ __launch_bounds__(256, 2) void attn_mma_kernel(
    const float* __restrict__ qkv, const int* __restrict__ mask,
    float* __restrict__ o)
{
    extern __shared__ float sA[];
    const uint32_t sbase = smem_u32(sA);
    float* Ps = sA + PS_OFF;
    uint32_t* PsU = (uint32_t*)Ps;
    const uint32_t* KsU = (const uint32_t*)(sA + KS_OFF);
    const uint32_t* VsU = (const uint32_t*)(sA + VS_OFF);
    int* Msk = (int*)(sA + MSK_OFF);

    const int b  = blockIdx.z;
    const int h  = blockIdx.y;
    const int qt = blockIdx.x;
    const int tid = threadIdx.x;
    const int w   = tid >> 5;
    const int lid = tid & 31;
    const int g   = lid >> 2;
    const int tg  = lid & 3;

    const int qr0 = w * 16 + g;
    const int qr1 = qr0 + 8;

    // ---- stage Q tile (128x64) into Ps via cp.async ----
    const float* Qg = qkv + ((size_t)(b * SEQ + qt * 128)) * QKVLD + h * HDIM;
    {
        const uint32_t pB = sbase + PS_OFF * 4;
        #pragma unroll
        for (int i = 0; i < 8; i++) {
            int idx = tid + i * 256;
            int r = idx >> 4, sg = idx & 15;
            cp16(pB + (uint32_t)(r * ALDP + sg * 4) * 4, Qg + (size_t)r * QKVLD + sg * 4);
        }
    }
    CP_COMMIT();

    // ---- KV tile loader ----
    auto load_kv = [&](int it, int st) {
        const float* Kg = qkv + ((size_t)(b * SEQ + it * AKEYS)) * QKVLD + DIM   + h * HDIM;
        const float* Vg = qkv + ((size_t)(b * SEQ + it * AKEYS)) * QKVLD + 2*DIM + h * HDIM;
        const uint32_t kB = sbase + (uint32_t)(KS_OFF + st * AKEYS * ALDK) * 4;
        const uint32_t vB = sbase + (uint32_t)(VS_OFF + st * AKEYS * ALDV) * 4;
        #pragma unroll
        for (int i = 0; i < 4; i++) {
            int idx = tid + i * 256;
            int r = idx >> 4, sg = idx & 15;
            cp16(kB + (uint32_t)(r * ALDK + sg * 4) * 4, Kg + (size_t)r * QKVLD + sg * 4);
            cp16(vB + (uint32_t)(r * ALDV + sg * 4) * 4, Vg + (size_t)r * QKVLD + sg * 4);
        }
        if (tid < 16)
            cp16(sbase + (uint32_t)(MSK_OFF + st * 64) * 4 + tid * 16,
                 mask + b * SEQ + it * AKEYS + tid * 4);
    };

    load_kv(0, 0); CP_COMMIT();
    CP_WAIT1();                // Q group done
    __syncthreads();

    // ---- preload Q fragments (base-2 scale folded) ----
    uint32_t aq[8][4];
    #pragma unroll
    for (int ks = 0; ks < 8; ks++) {
        const float* qr = Ps + qr0 * ALDP + ks * 8;
        aq[ks][0] = f2tf32(QSCALE2 * qr[tg]);
        aq[ks][1] = f2tf32(QSCALE2 * qr[8 * ALDP + tg]);
        aq[ks][2] = f2tf32(QSCALE2 * qr[tg + 4]);
        aq[ks][3] = f2tf32(QSCALE2 * qr[8 * ALDP + tg + 4]);
    }

    float m0 = -3.0e38f, m1 = -3.0e38f, l0 = 0.0f, l1 = 0.0f;
    float oacc[8][4] = {};

    for (int it = 0; it < NKT; it++) {
        __syncthreads();
        if (it + 1 < NKT) { load_kv(it + 1, (it + 1) & 1); CP_COMMIT(); }
        if (it + 1 < NKT) { CP_WAIT1(); } else { CP_WAIT0(); }
        __syncthreads();

        const int st = it & 1;
        const uint32_t* Kt = KsU + st * AKEYS * ALDK;
        const uint32_t* Vt = VsU + st * AKEYS * ALDV;
        const int*      Mi = Msk + st * 64;

        // ---- S = Q @ K^T (scores in log2 units) ----
        float sacc[8][4] = {};
        #pragma unroll
        for (int nt = 0; nt < 8; nt++) {
            const uint32_t* kr = Kt + (nt * 8 + g) * ALDK;
            #pragma unroll
            for (int ks = 0; ks < 8; ks++) {
                uint32_t b0 = kr[ks * 8 + tg];
                uint32_t b1 = kr[ks * 8 + tg + 4];
                mma_tf32(sacc[nt], aq[ks][0], aq[ks][1], aq[ks][2], aq[ks][3], b0, b1);
            }
        }

        // ---- mask ----
        #pragma unroll
        for (int nt = 0; nt < 8; nt++) {
            int c = nt * 8 + 2 * tg;
            if (Mi[c]     == 0) { sacc[nt][0] = -3.0e38f; sacc[nt][2] = -3.0e38f; }
            if (Mi[c + 1] == 0) { sacc[nt][1] = -3.0e38f; sacc[nt][3] = -3.0e38f; }
        }

        // ---- online softmax (base-2, quad-reduced) ----
        float tm0 = -3.0e38f, tm1 = -3.0e38f;
        #pragma unroll
        for (int nt = 0; nt < 8; nt++) {
            tm0 = fmaxf(tm0, fmaxf(sacc[nt][0], sacc[nt][1]));
            tm1 = fmaxf(tm1, fmaxf(sacc[nt][2], sacc[nt][3]));
        }
        tm0 = fmaxf(tm0, __shfl_xor_sync(0xffffffffu, tm0, 1));
        tm0 = fmaxf(tm0, __shfl_xor_sync(0xffffffffu, tm0, 2));
        tm1 = fmaxf(tm1, __shfl_xor_sync(0xffffffffu, tm1, 1));
        tm1 = fmaxf(tm1, __shfl_xor_sync(0xffffffffu, tm1, 2));

        float mn0 = fmaxf(m0, tm0), mn1 = fmaxf(m1, tm1);
        float corr0 = exp2f(m0 - mn0), corr1 = exp2f(m1 - mn1);
        m0 = mn0; m1 = mn1;

        float sum0 = 0.0f, sum1 = 0.0f;
        #pragma unroll
        for (int nt = 0; nt < 8; nt++) {
            float p0 = exp2f(sacc[nt][0] - mn0);
            float p1 = exp2f(sacc[nt][1] - mn0);
            float p2 = exp2f(sacc[nt][2] - mn1);
            float p3 = exp2f(sacc[nt][3] - mn1);
            sum0 += p0 + p1; sum1 += p2 + p3;
            int c = nt * 8 + 2 * tg;
            PsU[qr0 * ALDP + c]     = f2tf32(p0);
            PsU[qr0 * ALDP + c + 1] = f2tf32(p1);
            PsU[qr1 * ALDP + c]     = f2tf32(p2);
            PsU[qr1 * ALDP + c + 1] = f2tf32(p3);
        }
        sum0 += __shfl_xor_sync(0xffffffffu, sum0, 1);
        sum0 += __shfl_xor_sync(0xffffffffu, sum0, 2);
        sum1 += __shfl_xor_sync(0xffffffffu, sum1, 1);
        sum1 += __shfl_xor_sync(0xffffffffu, sum1, 2);
        l0 = l0 * corr0 + sum0;
        l1 = l1 * corr1 + sum1;

        // ---- rescale O ----
        #pragma unroll
        for (int dt = 0; dt < 8; dt++) {
            oacc[dt][0] *= corr0; oacc[dt][1] *= corr0;
            oacc[dt][2] *= corr1; oacc[dt][3] *= corr1;
        }
        __syncwarp();

        // ---- O += P @ V ----
        #pragma unroll
        for (int kt = 0; kt < 8; kt++) {
            uint32_t a0 = PsU[qr0 * ALDP + kt * 8 + tg];
            uint32_t a1 = PsU[qr1 * ALDP + kt * 8 + tg];
            uint32_t a2 = PsU[qr0 * ALDP + kt * 8 + tg + 4];
            uint32_t a3 = PsU[qr1 * ALDP + kt * 8 + tg + 4];
            const uint32_t* vr0 = Vt + (kt * 8 + tg) * ALDV;
            const uint32_t* vr1 = Vt + (kt * 8 + tg + 4) * ALDV;
            #pragma unroll
            for (int dt = 0; dt < 8; dt++) {
                mma_tf32(oacc[dt], a0, a1, a2, a3, vr0[dt * 8 + g], vr1[dt * 8 + g]);
            }
        }
        __syncwarp();
    }

    // ---- epilogue (store tf32-rounded bits; Wo GEMM consumes raw) ----
    const float inv0 = 1.0f / l0, inv1 = 1.0f / l1;
    float* Og = o + ((size_t)(b * SEQ + qt * 128)) * DIM + h * HDIM;
    #pragma unroll
    for (int dt = 0; dt < 8; dt++) {
        int c = dt * 8 + 2 * tg;
        float2 lo, hi;
        lo.x = __uint_as_float(f2tf32(oacc[dt][0] * inv0));
        lo.y = __uint_as_float(f2tf32(oacc[dt][1] * inv0));
        hi.x = __uint_as_float(f2tf32(oacc[dt][2] * inv1));
        hi.y = __uint_as_float(f2tf32(oacc[dt][3] * inv1));
        *(float2*)(Og + (size_t)qr0 * DIM + c) = lo;
        *(float2*)(Og + (size_t)qr1 * DIM + c) = hi;
    }
}

// ---------------------------------------------------------------------------
// kernel_launch
// ---------------------------------------------------------------------------
extern "C" void kernel_launch(void* const* d_in, const int* in_sizes, int n_in,
                              void* d_out, int out_size)
{
    const float* H    = (const float*)d_in[0];
    const int*   mask = (const int*)  d_in[1];
    const float* Wq   = (const float*)d_in[2];
    const float* Wk   = (const float*)d_in[3];
    const float* Wv   = (const float*)d_in[4];
    const float* Wo   = (const float*)d_in[5];
    float* out = (float*)d_out;

    float *qkv, *ao, *hr, *wt;
    cudaGetSymbolAddress((void**)&qkv, g_qkv);
    cudaGetSymbolAddress((void**)&ao,  g_ao);
    cudaGetSymbolAddress((void**)&hr,  g_hr);
    cudaGetSymbolAddress((void**)&wt,  g_wt);
    float* wto = wt + 3 * DIM * DIM;

    cudaFuncSetAttribute(gemm_mma_kernel<true>,
                         cudaFuncAttributeMaxDynamicSharedMemorySize, GEMM_SMEM);
    cudaFuncSetAttribute(gemm_mma_kernel<false>,
                         cudaFuncAttributeMaxDynamicSharedMemorySize, GEMM_SMEM);
    cudaFuncSetAttribute(attn_mma_kernel,
                         cudaFuncAttributeMaxDynamicSharedMemorySize, ATT_SMEM);

    // Pre-round H; transpose+round weights
    const int n4 = MROWS * DIM / 4;
    round_tf32_kernel<<<(n4 + 255) / 256, 256>>>((const float4*)H, (float4*)hr, n4);
    dim3 tb(32, 8), tg(DIM / 32, DIM / 32, 4);
    transpose4_kernel<<<tg, tb>>>(Wq, Wk, Wv, Wo, wt);

    // Fused QKV projection: [4096, 3072], tf32-rounded outputs
    dim3 gqkv(QKVLD / BN, MROWS / BM);   // (24, 32)
    gemm_mma_kernel<true><<<gqkv, 256, GEMM_SMEM>>>(hr, wt, qkv, QKVLD);

    dim3 ga(SEQ / 128, HEADS, BATCH);    // (16, 16, 2)
    attn_mma_kernel<<<ga, 256, ATT_SMEM>>>(qkv, mask, ao);

    dim3 go(DIM / BN, MROWS / BM);       // (8, 32)
    gemm_mma_kernel<false><<<go, 256, GEMM_SMEM>>>(ao, wto, out, DIM);
}